// round 17
// baseline (speedup 1.0000x reference)
#include <cuda_runtime.h>
#include <cuda_bf16.h>
#include <cstdint>

#define MAXN 50000
#define MAXE 800000
#define MAXT 391            // ceil(MAXN/128)

// ---------------- device scratch ----------------
__device__ float d_xl[MAXN * 256];
__device__ float d_xr[MAXN * 256];
__device__ float d_h2[MAXN * 256];
__device__ int   d_cnt[MAXN];
__device__ float d_loopsum[MAXN];
__device__ float d_loopa[MAXN];
__device__ int   d_rowptr[MAXN + 1];
__device__ int   d_pos[MAXN];
__device__ int   d_csrc[MAXE];
__device__ float d_cea[MAXE];
__device__ float d_gsum[64 * 256];
__device__ float d_gcnt[64];
// bf16 hi/lo images, padded to full 128-row tiles
__device__ __align__(16) unsigned short d_ahi[MAXT * 128 * 256];
__device__ __align__(16) unsigned short d_alo[MAXT * 128 * 256];
// transposed combined weights Wt[n][k] (n: 0-255 = wl cols, 256-511 = wr cols)
__device__ __align__(16) unsigned short d_w1hi[512 * 64],  d_w1lo[512 * 64];
__device__ __align__(16) unsigned short d_w2hi[512 * 256], d_w2lo[512 * 256];

// ---------------- helpers ----------------
__device__ __forceinline__ uint32_t smem_u32(const void* p) {
    uint32_t a;
    asm("{ .reg .u64 t; cvta.to.shared.u64 t, %1; cvt.u32.u64 %0, t; }" : "=r"(a) : "l"(p));
    return a;
}
__device__ __forceinline__ void ldsm4(uint32_t* r, uint32_t addr) {
    asm volatile("ldmatrix.sync.aligned.m8n8.x4.shared.b16 {%0,%1,%2,%3}, [%4];"
                 : "=r"(r[0]), "=r"(r[1]), "=r"(r[2]), "=r"(r[3]) : "r"(addr));
}
__device__ __forceinline__ void mma_bf16(float* c, const uint32_t* a, uint32_t b0, uint32_t b1) {
    asm volatile("mma.sync.aligned.m16n8k16.row.col.f32.bf16.bf16.f32 "
                 "{%0,%1,%2,%3}, {%4,%5,%6,%7}, {%8,%9}, {%0,%1,%2,%3};"
                 : "+f"(c[0]), "+f"(c[1]), "+f"(c[2]), "+f"(c[3])
                 : "r"(a[0]), "r"(a[1]), "r"(a[2]), "r"(a[3]), "r"(b0), "r"(b1));
}
__device__ __forceinline__ void cp16(uint32_t saddr, const void* gaddr) {
    asm volatile("cp.async.cg.shared.global [%0], [%1], 16;" :: "r"(saddr), "l"(gaddr));
}
__device__ __forceinline__ void cp_commit() {
    asm volatile("cp.async.commit_group;");
}
template <int Nw>
__device__ __forceinline__ void cp_wait() {
    asm volatile("cp.async.wait_group %0;" :: "n"(Nw));
}
__device__ __forceinline__ void split_bf16(float v, unsigned short& h, unsigned short& l) {
    __nv_bfloat16 hb = __float2bfloat16_rn(v);
    float r = v - __bfloat162float(hb);
    __nv_bfloat16 lb = __float2bfloat16_rn(r);
    h = __bfloat16_as_ushort(hb);
    l = __bfloat16_as_ushort(lb);
}

// ---------------- prep: zero(cnt,loopsum) + encoder->A image + W1 image ----------------
__global__ void prep_kernel(const float* __restrict__ x,
                            const float* __restrict__ enc_w, const float* __restrict__ enc_b,
                            const float* __restrict__ wl, const float* __restrict__ wr,
                            unsigned short* __restrict__ ahi, unsigned short* __restrict__ alo,
                            unsigned short* __restrict__ w1hi, unsigned short* __restrict__ w1lo,
                            int* __restrict__ cnt, float* __restrict__ loopsum, int N) {
    int gid = blockIdx.x * blockDim.x + threadIdx.x;
    int N8 = N * 8;
    if (gid < N8) {
        int i = gid >> 3, g = gid & 7;
        float4 xv = *(const float4*)(x + (size_t)i * 4);
        uint32_t hv[4], lv[4];
#pragma unroll
        for (int q = 0; q < 4; q++) {
            unsigned short hh[2], ll[2];
#pragma unroll
            for (int u = 0; u < 2; u++) {
                int j = g * 8 + q * 2 + u;
                float s = enc_b[j] + xv.x * enc_w[j] + xv.y * enc_w[64 + j]
                        + xv.z * enc_w[128 + j] + xv.w * enc_w[192 + j];
                s = fmaxf(s, 0.f);
                split_bf16(s, hh[u], ll[u]);
            }
            hv[q] = (uint32_t)hh[0] | ((uint32_t)hh[1] << 16);
            lv[q] = (uint32_t)ll[0] | ((uint32_t)ll[1] << 16);
        }
        size_t off = (size_t)i * 64 + g * 8;
        *(uint4*)(ahi + off) = make_uint4(hv[0], hv[1], hv[2], hv[3]);
        *(uint4*)(alo + off) = make_uint4(lv[0], lv[1], lv[2], lv[3]);
        return;
    }
    int gid2 = gid - N8;
    if (gid2 < 4096) {
        int n = gid2 >> 3, g = gid2 & 7;
        int ks = g * 8;
        const float* src = (n < 256) ? wl : wr;
        int col = n & 255;
        uint32_t hv[4], lv[4];
#pragma unroll
        for (int q = 0; q < 4; q++) {
            float v0 = src[(size_t)(ks + 2 * q) * 256 + col];
            float v1 = src[(size_t)(ks + 2 * q + 1) * 256 + col];
            unsigned short h0, l0, h1, l1;
            split_bf16(v0, h0, l0);
            split_bf16(v1, h1, l1);
            hv[q] = (uint32_t)h0 | ((uint32_t)h1 << 16);
            lv[q] = (uint32_t)l0 | ((uint32_t)l1 << 16);
        }
        size_t off = (size_t)n * 64 + ks;
        *(uint4*)(w1hi + off) = make_uint4(hv[0], hv[1], hv[2], hv[3]);
        *(uint4*)(w1lo + off) = make_uint4(lv[0], lv[1], lv[2], lv[3]);
        return;
    }
    int gid3 = gid2 - 4096;
    if (gid3 < N) {
        cnt[gid3] = 0;
        loopsum[gid3] = 0.f;
    }
}

// ---------------- CSR build ----------------
__global__ void count_kernel(const int* __restrict__ ei, const float* __restrict__ eattr,
                             int* __restrict__ cnt, float* __restrict__ loopsum, int E) {
    int e = blockIdx.x * blockDim.x + threadIdx.x;
    if (e >= E) return;
    int dst = ei[E + e];
    atomicAdd(cnt + dst, 1);
    atomicAdd(loopsum + dst, eattr[e]);
}

__global__ __launch_bounds__(1024) void scan_kernel(
    const int* __restrict__ cnt, const float* __restrict__ loopsum,
    int* __restrict__ rowptr, int* __restrict__ pos, float* __restrict__ loopa,
    int N, int E) {
    __shared__ int part[1024];
    int t = threadIdx.x;
    int chunk = (N + 1023) / 1024;
    int b0 = t * chunk, b1 = min(b0 + chunk, N);
    int s = 0;
    for (int j = b0; j < b1; j++) s += cnt[j];
    part[t] = s;
    __syncthreads();
    for (int off = 1; off < 1024; off <<= 1) {
        int v = (t >= off) ? part[t - off] : 0;
        __syncthreads();
        part[t] += v;
        __syncthreads();
    }
    int run = (t == 0) ? 0 : part[t - 1];
    for (int j = b0; j < b1; j++) {
        rowptr[j] = run;
        pos[j] = run;
        int c = cnt[j];
        loopa[j] = loopsum[j] / (float)max(c, 1);
        run += c;
    }
    if (t == 1023) rowptr[N] = E;
}

__global__ void scatter_kernel(const int* __restrict__ ei, const float* __restrict__ eattr,
                               int* __restrict__ pos,
                               int* __restrict__ csrc, float* __restrict__ cea, int E) {
    int e = blockIdx.x * blockDim.x + threadIdx.x;
    if (e >= E) return;
    int dst = ei[E + e];
    int p = atomicAdd(pos + dst, 1);
    csrc[p] = ei[e];
    cea[p] = eattr[e];
}

// ---------------- W [K,256] x2 -> combined transposed Wt[n][k] bf16 hi/lo ----------------
__global__ void conv_w_kernel(const float* __restrict__ wl, const float* __restrict__ wr,
                              int K,
                              unsigned short* __restrict__ hi, unsigned short* __restrict__ lo) {
    int gpr = K >> 3;
    int total = 512 * gpr;
    int gid = blockIdx.x * blockDim.x + threadIdx.x;
    if (gid >= total) return;
    int n = gid / gpr, g = gid % gpr;
    int ks = g * 8;
    const float* src = (n < 256) ? wl : wr;
    int col = n & 255;
    uint32_t hv[4], lv[4];
#pragma unroll
    for (int q = 0; q < 4; q++) {
        float v0 = src[(size_t)(ks + 2 * q) * 256 + col];
        float v1 = src[(size_t)(ks + 2 * q + 1) * 256 + col];
        unsigned short h0, l0, h1, l1;
        split_bf16(v0, h0, l0);
        split_bf16(v1, h1, l1);
        hv[q] = (uint32_t)h0 | ((uint32_t)h1 << 16);
        lv[q] = (uint32_t)l0 | ((uint32_t)l1 << 16);
    }
    size_t off = (size_t)n * K + ks;
    *(uint4*)(hi + off) = make_uint4(hv[0], hv[1], hv[2], hv[3]);
    *(uint4*)(lo + off) = make_uint4(lv[0], lv[1], lv[2], lv[3]);
}

// ---------------- mma.sync dual GEMM, cp.async 4-buffer depth-3 pipeline, 2 CTA/SM ----------------
#define SROW 24                   // ushorts per smem row (48B stride, conflict-free ldmatrix)
#define BUFBYTES (128 * SROW * 2) // 6144 bytes per buffer
#define GEMM_DYN (16 * BUFBYTES)  // 4 regions x 4 buffers = 98304 bytes
__global__ __launch_bounds__(256, 2) void gemm_mma_kernel(
    const unsigned short* __restrict__ ahi, const unsigned short* __restrict__ alo,
    const unsigned short* __restrict__ whi, const unsigned short* __restrict__ wlo,
    const float* __restrict__ bl, const float* __restrict__ br,
    float* __restrict__ xl, float* __restrict__ xr, int M, int K) {
    extern __shared__ __align__(16) unsigned char dsm[];
    uint32_t base = smem_u32(dsm);

    int tid = threadIdx.x, lane = tid & 31, wid = tid >> 5;
    int wm = wid & 3, wn = wid >> 2;
    int row0 = blockIdx.y * 128, bn0 = blockIdx.x * 128;

    float acc[2][8][4];
#pragma unroll
    for (int t = 0; t < 2; t++)
#pragma unroll
        for (int j = 0; j < 8; j++)
#pragma unroll
            for (int q = 0; q < 4; q++) acc[t][j][q] = 0.f;

    int srow = tid >> 1, kh = (tid & 1) << 3;
    uint32_t soff = (uint32_t)((srow * 3 + (tid & 1)) * 16);
    const int nstage = K >> 4;

    uint32_t aoff = (uint32_t)((lane & 15) * 48 + ((lane >> 4) << 4));
    uint32_t boff = (uint32_t)((((lane >> 4) << 3) + (lane & 7)) * 48 + (((lane >> 3) & 1) << 4));

    size_t gA = (size_t)(row0 + srow) * K + kh;
    size_t gB = (size_t)(bn0 + srow) * K + kh;

    auto Ah = [&](int b) { return base + (uint32_t)(b * BUFBYTES); };
    auto Al = [&](int b) { return base + (uint32_t)((4 + b) * BUFBYTES); };
    auto Bh = [&](int b) { return base + (uint32_t)((8 + b) * BUFBYTES); };
    auto Bl = [&](int b) { return base + (uint32_t)((12 + b) * BUFBYTES); };

    auto issue = [&](int s) {
        if (s < nstage) {
            int b = s & 3;
            size_t o = (size_t)s * 16;
            cp16(Ah(b) + soff, ahi + gA + o);
            cp16(Al(b) + soff, alo + gA + o);
            cp16(Bh(b) + soff, whi + gB + o);
            cp16(Bl(b) + soff, wlo + gB + o);
        }
        cp_commit();                 // always commit: group count stays exact
    };

    issue(0); issue(1); issue(2);

    for (int s = 0; s < nstage; s++) {
        issue(s + 3);                // buffer (s+3)&3 != s,s+1,s+2 mod 4
        cp_wait<3>();                // group s retired
        __syncthreads();

        int b = s & 3;
        uint32_t a_hi[2][4], a_lo[2][4];
#pragma unroll
        for (int t = 0; t < 2; t++) {
            uint32_t ra = (uint32_t)((wm * 32 + t * 16) * 48);
            ldsm4(a_hi[t], Ah(b) + ra + aoff);
            ldsm4(a_lo[t], Al(b) + ra + aoff);
        }
#pragma unroll
        for (int bp = 0; bp < 4; bp++) {
            uint32_t rb = (uint32_t)((wn * 64 + bp * 16) * 48);
            uint32_t bh[4], blo[4];
            ldsm4(bh, Bh(b) + rb + boff);
            ldsm4(blo, Bl(b) + rb + boff);
#pragma unroll
            for (int t = 0; t < 2; t++) {
                mma_bf16(acc[t][2 * bp],     a_hi[t], bh[0], bh[1]);
                mma_bf16(acc[t][2 * bp + 1], a_hi[t], bh[2], bh[3]);
                mma_bf16(acc[t][2 * bp],     a_lo[t], bh[0], bh[1]);
                mma_bf16(acc[t][2 * bp + 1], a_lo[t], bh[2], bh[3]);
                mma_bf16(acc[t][2 * bp],     a_hi[t], blo[0], blo[1]);
                mma_bf16(acc[t][2 * bp + 1], a_hi[t], blo[2], blo[3]);
            }
        }
        __syncthreads();             // all warps done with buffer b before it is re-filled
    }

    // epilogue
#pragma unroll
    for (int t = 0; t < 2; t++) {
#pragma unroll
        for (int j = 0; j < 8; j++) {
            int gc = bn0 + wn * 64 + j * 8 + ((lane & 3) << 1);
            int cc = (gc < 256) ? gc : gc - 256;
            float* basep = (gc < 256) ? xl : xr;
            const float* bias = (gc < 256) ? bl : br;
            float b0 = bias[cc], b1 = bias[cc + 1];
#pragma unroll
            for (int h = 0; h < 2; h++) {
                int gm = row0 + wm * 32 + t * 16 + (lane >> 2) + h * 8;
                if (gm < M) {
                    float2 v = make_float2(acc[t][j][2 * h] + b0, acc[t][j][2 * h + 1] + b1);
                    *(float2*)(basep + (size_t)gm * 256 + cc) = v;
                }
            }
        }
    }
}

// ---------------- CSR edge pass: per-warp cp.async ring (depth 4), fully fused ----------------
// If ohi != nullptr, outputs bf16 hi/lo images (row-major [N,256]) for the next GEMM;
// otherwise outputs fp32 to `out`.
#define EDEPTH 4
__global__ __launch_bounds__(256) void edge_csr_kernel(
    const int* __restrict__ rowptr, const int* __restrict__ csrc,
    const float* __restrict__ cea, const float* __restrict__ loopa,
    const float* __restrict__ xl, const float* __restrict__ xr,
    const float* __restrict__ we, const float* __restrict__ att,
    const float* __restrict__ bias, float* __restrict__ out,
    unsigned short* __restrict__ ohi, unsigned short* __restrict__ olo, int N) {
    __shared__ __align__(16) float ring[8][EDEPTH][256];   // 32KB
    int lane = threadIdx.x & 31;
    int wib = threadIdx.x >> 5;
    int warp = (blockIdx.x * blockDim.x + threadIdx.x) >> 5;
    int nw = (gridDim.x * blockDim.x) >> 5;
    int c0 = lane << 3;
    float wef[8], attf[8], bf[8];
#pragma unroll
    for (int q = 0; q < 8; q++) {
        wef[q] = we[c0 + q]; attf[q] = att[c0 + q]; bf[q] = bias[c0 + q];
    }
    uint32_t ringbase = smem_u32(&ring[wib][0][0]);
    uint32_t myoff = (uint32_t)(lane * 32);

    for (int i = warp; i < N; i += nw) {
        const float* pr = xr + (size_t)i * 256 + c0;
        float4 r0 = *(const float4*)pr;
        float4 r1 = *(const float4*)(pr + 4);
        float rv[8] = {r0.x, r0.y, r0.z, r0.w, r1.x, r1.y, r1.z, r1.w};
        float acc[8] = {0, 0, 0, 0, 0, 0, 0, 0};
        float den = 0.f;

        int rb = rowptr[i];
        int deg = rowptr[i + 1] - rb;
        int total = deg + 1;               // + self loop (edge index 'deg')
        float la = loopa[i];

        auto issue = [&](int k) {
            if (k < total) {
                int s = (k < deg) ? __ldg(csrc + rb + k) : i;
                const float* p = xl + (size_t)s * 256 + c0;
                uint32_t dst = ringbase + (uint32_t)((k & (EDEPTH - 1)) * 1024) + myoff;
                cp16(dst, p);
                cp16(dst + 16, p + 4);
            }
            cp_commit();                   // always commit (empty groups keep count exact)
        };
        issue(0); issue(1); issue(2); issue(3);

        for (int k = 0; k < total; k++) {
            cp_wait<EDEPTH - 1>();
            float ea = (k < deg) ? __ldg(cea + rb + k) : la;
            const float* slot = &ring[wib][k & (EDEPTH - 1)][c0];
            float4 A0 = *(const float4*)slot;
            float4 A1 = *(const float4*)(slot + 4);
            float lv[8] = {A0.x, A0.y, A0.z, A0.w, A1.x, A1.y, A1.z, A1.w};
            float a = 0.f;
#pragma unroll
            for (int q = 0; q < 8; q++) {
                float m = lv[q] + rv[q] + ea * wef[q];
                m = (m > 0.f) ? m : 0.2f * m;   // leaky_relu 0.2
                a += m * attf[q];
            }
            a += __shfl_xor_sync(0xffffffffu, a, 1);
            a += __shfl_xor_sync(0xffffffffu, a, 2);
            a += __shfl_xor_sync(0xffffffffu, a, 4);
            float ex = __expf(a);          // softmax shift-invariant; alpha small
            den += ex;
#pragma unroll
            for (int q = 0; q < 8; q++) acc[q] += ex * lv[q];
            issue(k + EDEPTH);
        }

        float inv = 1.0f / den;
        float o[8];
#pragma unroll
        for (int q = 0; q < 8; q++) o[q] = fmaxf(acc[q] * inv + bf[q], 0.f);
        if (ohi) {
            uint32_t hv[4], lv4[4];
#pragma unroll
            for (int q = 0; q < 4; q++) {
                unsigned short h0, l0, h1, l1;
                split_bf16(o[2 * q], h0, l0);
                split_bf16(o[2 * q + 1], h1, l1);
                hv[q] = (uint32_t)h0 | ((uint32_t)h1 << 16);
                lv4[q] = (uint32_t)l0 | ((uint32_t)l1 << 16);
            }
            size_t off = (size_t)i * 256 + c0;
            *(uint4*)(ohi + off) = make_uint4(hv[0], hv[1], hv[2], hv[3]);
            *(uint4*)(olo + off) = make_uint4(lv4[0], lv4[1], lv4[2], lv4[3]);
        } else {
            float* po = out + (size_t)i * 256 + c0;
            *(float4*)(po)     = *(float4*)(o);
            *(float4*)(po + 4) = *(float4*)(o + 4);
        }
    }
}

// ---------------- global mean pool ----------------
__global__ __launch_bounds__(256) void pool_kernel(
    const float* __restrict__ h, const int* __restrict__ batch,
    float* __restrict__ gsum, float* __restrict__ gcnt, int N) {
    __shared__ int sb[256];
    int t = threadIdx.x;
    int start = blockIdx.x * 256;
    int end = min(start + 256, N);
    int n = end - start;
    if (n <= 0) return;
    if (t < n) sb[t] = batch[start + t];
    __syncthreads();
    float acc = 0.f, cnt = 0.f;
    int cur = sb[0];
    for (int i = 0; i < n; i++) {
        int b = sb[i];
        if (b != cur) {
            atomicAdd(gsum + (size_t)cur * 256 + t, acc);
            if (t == 0) atomicAdd(gcnt + cur, cnt);
            acc = 0.f; cnt = 0.f; cur = b;
        }
        acc += h[(size_t)(start + i) * 256 + t];
        cnt += 1.f;
    }
    atomicAdd(gsum + (size_t)cur * 256 + t, acc);
    if (t == 0) atomicAdd(gcnt + cur, cnt);
}

// ---------------- final MLP ----------------
__global__ __launch_bounds__(128) void mlp_kernel(
    const float* __restrict__ gsum, const float* __restrict__ gcnt,
    const float* __restrict__ p1w, const float* __restrict__ p1b,
    const float* __restrict__ lng, const float* __restrict__ lnb,
    const float* __restrict__ p2w, const float* __restrict__ p2b,
    float* __restrict__ out) {
    __shared__ float gs[256];
    __shared__ float zs[128];
    __shared__ float wsum[4], wsum2[4];
    int b = blockIdx.x, t = threadIdx.x;
    float invc = 1.0f / fmaxf(gcnt[b], 1.0f);
    gs[t] = gsum[(size_t)b * 256 + t] * invc;
    gs[t + 128] = gsum[(size_t)b * 256 + 128 + t] * invc;
    __syncthreads();
    float z = p1b[t];
    for (int k = 0; k < 256; k++) z += gs[k] * p1w[(size_t)k * 128 + t];
    float s = z, s2 = z * z;
#pragma unroll
    for (int o = 16; o; o >>= 1) {
        s += __shfl_xor_sync(0xffffffffu, s, o);
        s2 += __shfl_xor_sync(0xffffffffu, s2, o);
    }
    if ((t & 31) == 0) { wsum[t >> 5] = s; wsum2[t >> 5] = s2; }
    __syncthreads();
    s = wsum[0] + wsum[1] + wsum[2] + wsum[3];
    s2 = wsum2[0] + wsum2[1] + wsum2[2] + wsum2[3];
    float mu = s * (1.0f / 128.0f);
    float var = s2 * (1.0f / 128.0f) - mu * mu;
    float zn = (z - mu) * rsqrtf(var + 1e-5f) * lng[t] + lnb[t];
    zs[t] = fmaxf(zn, 0.f);
    __syncthreads();
    if (t < 64) {
        float o = p2b[t];
        for (int j = 0; j < 128; j++) o += zs[j] * p2w[(size_t)j * 64 + t];
        out[(size_t)b * 64 + t] = fmaxf(o, 0.f);
    }
}

extern "C" void kernel_launch(void* const* d_in, const int* in_sizes, int n_in,
                              void* d_out, int out_size) {
    const float* x      = (const float*)d_in[0];
    const int*   ei     = (const int*)d_in[1];
    const float* eattr  = (const float*)d_in[2];
    const int*   batch  = (const int*)d_in[3];
    const float* enc_w  = (const float*)d_in[4];
    const float* enc_b  = (const float*)d_in[5];
    const float* g1_wl  = (const float*)d_in[6];
    const float* g1_bl  = (const float*)d_in[7];
    const float* g1_wr  = (const float*)d_in[8];
    const float* g1_br  = (const float*)d_in[9];
    const float* g1_we  = (const float*)d_in[10];
    const float* g1_att = (const float*)d_in[11];
    const float* g1_bias= (const float*)d_in[12];
    const float* g2_wl  = (const float*)d_in[13];
    const float* g2_bl  = (const float*)d_in[14];
    const float* g2_wr  = (const float*)d_in[15];
    const float* g2_br  = (const float*)d_in[16];
    const float* g2_we  = (const float*)d_in[17];
    const float* g2_att = (const float*)d_in[18];
    const float* g2_bias= (const float*)d_in[19];
    const float* p1_w   = (const float*)d_in[20];
    const float* p1_b   = (const float*)d_in[21];
    const float* ln_g   = (const float*)d_in[22];
    const float* ln_b   = (const float*)d_in[23];
    const float* p2_w   = (const float*)d_in[24];
    const float* p2_b   = (const float*)d_in[25];

    int N = in_sizes[3];
    int E = in_sizes[2];
    int NG_ = out_size / 64;

    float *xl, *xr, *h2, *loopsum, *loopa, *cea, *gsum, *gcnt;
    int *cnt, *rowptr, *pos, *csrc;
    unsigned short *ahi, *alo, *w1hi, *w1lo, *w2hi, *w2lo;
    cudaGetSymbolAddress((void**)&xl, d_xl);
    cudaGetSymbolAddress((void**)&xr, d_xr);
    cudaGetSymbolAddress((void**)&h2, d_h2);
    cudaGetSymbolAddress((void**)&cnt, d_cnt);
    cudaGetSymbolAddress((void**)&loopsum, d_loopsum);
    cudaGetSymbolAddress((void**)&loopa, d_loopa);
    cudaGetSymbolAddress((void**)&rowptr, d_rowptr);
    cudaGetSymbolAddress((void**)&pos, d_pos);
    cudaGetSymbolAddress((void**)&csrc, d_csrc);
    cudaGetSymbolAddress((void**)&cea, d_cea);
    cudaGetSymbolAddress((void**)&gsum, d_gsum);
    cudaGetSymbolAddress((void**)&gcnt, d_gcnt);
    cudaGetSymbolAddress((void**)&ahi, d_ahi);
    cudaGetSymbolAddress((void**)&alo, d_alo);
    cudaGetSymbolAddress((void**)&w1hi, d_w1hi);
    cudaGetSymbolAddress((void**)&w1lo, d_w1lo);
    cudaGetSymbolAddress((void**)&w2hi, d_w2hi);
    cudaGetSymbolAddress((void**)&w2lo, d_w2lo);

    cudaFuncSetAttribute(gemm_mma_kernel, cudaFuncAttributeMaxDynamicSharedMemorySize,
                         GEMM_DYN);

    int ntiles = (N + 127) / 128;
    int eblocks = (N * 32 + 255) / 256;
    dim3 ggrid(4, ntiles);

    int preptot = N * 8 + 4096 + N;
    prep_kernel<<<(preptot + 255) / 256, 256>>>(x, enc_w, enc_b, g1_wl, g1_wr,
                                                ahi, alo, w1hi, w1lo, cnt, loopsum, N);
    count_kernel<<<(E + 255) / 256, 256>>>(ei, eattr, cnt, loopsum, E);
    scan_kernel<<<1, 1024>>>(cnt, loopsum, rowptr, pos, loopa, N, E);
    scatter_kernel<<<(E + 255) / 256, 256>>>(ei, eattr, pos, csrc, cea, E);
    gemm_mma_kernel<<<ggrid, 256, GEMM_DYN>>>(ahi, alo, w1hi, w1lo, g1_bl, g1_br,
                                              xl, xr, N, 64);
    // layer-1 edge pass writes the layer-2 A image directly (bf16 hi/lo)
    edge_csr_kernel<<<eblocks, 256>>>(rowptr, csrc, cea, loopa, xl, xr,
                                      g1_we, g1_att, g1_bias, nullptr, ahi, alo, N);

    // ---- GAT layer 2 (K = 256) ----
    conv_w_kernel<<<(512 * 32 + 255) / 256, 256>>>(g2_wl, g2_wr, 256, w2hi, w2lo);
    gemm_mma_kernel<<<ggrid, 256, GEMM_DYN>>>(ahi, alo, w2hi, w2lo, g2_bl, g2_br,
                                              xl, xr, N, 256);
    edge_csr_kernel<<<eblocks, 256>>>(rowptr, csrc, cea, loopa, xl, xr,
                                      g2_we, g2_att, g2_bias, h2, nullptr, nullptr, N);

    // ---- pool + MLP ----
    cudaMemsetAsync(gsum, 0, (size_t)NG_ * 256 * sizeof(float));
    cudaMemsetAsync(gcnt, 0, (size_t)NG_ * sizeof(float));
    pool_kernel<<<(N + 255) / 256, 256>>>(h2, batch, gsum, gcnt, N);
    mlp_kernel<<<NG_, 128>>>(gsum, gcnt, p1_w, p1_b, ln_g, ln_b, p2_w, p2_b, (float*)d_out);
}